// round 16
// baseline (speedup 1.0000x reference)
#include <cuda_runtime.h>
#include <cuda_fp16.h>
#include <math.h>
#include <stdint.h>

#define Bn 4
#define Cn 512
#define Nn 4096
#define TWO_C 1024
#define WN (Cn * Cn)

constexpr size_t SZ_BCN = (size_t)Bn * Cn * Nn;
constexpr size_t SZ_GB  = (size_t)Bn * TWO_C * Nn;
constexpr size_t SZ_S   = (size_t)Bn * Nn * Nn;

// ---- scratch ----
__device__ __half g_NCt[SZ_BCN];     // normed content^T [b][n][c]
__device__ __half g_NSt[SZ_BCN];     // normed style^T
__device__ __half g_St[SZ_BCN];      // raw style^T
__device__ __half g_Th[SZ_BCN];      // T = NCt . M'^T  [b][q][cj]
__device__ __half g_V[SZ_BCN];       // [b][c][s]
__device__ __half g_STYt[SZ_BCN];    // [b][q][c]
__device__ __half g_GBh[SZ_GB];      // gamma/beta, half
__device__ float  g_S[SZ_S];         // scores fp32 / probs half in place
__device__ __half g_WQt[WN];         // Wq^T (rows ci, K-major co)
__device__ __half g_WKt[WN];         // Wk^T
__device__ __half g_Mh[WN];          // M'[cj][ci] = sum_co Wk[co,cj] Wq[co,ci]
__device__ __half g_WV[WN];
__device__ __half g_WGB[TWO_C * Cn];
__device__ float  g_bGB[TWO_C];
__device__ float  g_uvc[2 * Cn + 1]; // u[0..C), v[C..2C), c0
__device__ float  g_rq[Bn * Nn];
__device__ float  g_cs[Bn * Nn];
__device__ float2 g_stats[2 * Bn * Cn];

// ===========================================================================
// helpers
// ===========================================================================
__device__ __forceinline__ uint32_t smem_u32(const void* p) {
    uint32_t a;
    asm("{ .reg .u64 t; cvta.to.shared.u64 t, %1; cvt.u32.u64 %0, t; }" : "=r"(a) : "l"(p));
    return a;
}
__device__ __forceinline__ void cpa16(uint32_t d, const void* s) {
    asm volatile("cp.async.cg.shared.global [%0], [%1], 16;\n" :: "r"(d), "l"(s));
}
#define CP_COMMIT() asm volatile("cp.async.commit_group;\n" ::: "memory")
#define CP_WAIT(n)  asm volatile("cp.async.wait_group %0;\n" :: "n"(n) : "memory")

__device__ __forceinline__ void mma_f16(float* c, const uint32_t* a, const uint32_t* b) {
    asm volatile(
        "mma.sync.aligned.m16n8k16.row.col.f32.f16.f16.f32 "
        "{%0,%1,%2,%3}, {%4,%5,%6,%7}, {%8,%9}, {%0,%1,%2,%3};"
        : "+f"(c[0]), "+f"(c[1]), "+f"(c[2]), "+f"(c[3])
        : "r"(a[0]), "r"(a[1]), "r"(a[2]), "r"(a[3]), "r"(b[0]), "r"(b[1]));
}
__device__ __forceinline__ void ldsm_x4(uint32_t& r0, uint32_t& r1, uint32_t& r2, uint32_t& r3,
                                        uint32_t addr) {
    asm volatile("ldmatrix.sync.aligned.m8n8.x4.shared.b16 {%0,%1,%2,%3}, [%4];"
                 : "=r"(r0), "=r"(r1), "=r"(r2), "=r"(r3) : "r"(addr));
}

#define STAGES2 4
#define AROW 72
#define OPER_H (128 * AROW)
#define STG_H  (2 * OPER_H)
#define DYN_SMEM2 (STAGES2 * STG_H * 2)   // 147456 B

// ===========================================================================
// v2 core: 512 threads, 1 CTA/SM, warp grid 4x4, warp 32x32, BK=64,
// 4-stage cp.async, double-buffered ldmatrix fragments.
// D[M,N] = A[M,K] * B[N,K]^T.
// bias_mode: 0 none, 1 row bias, 2 col bias, 3 row(bias)+col(bias2). relu; d_half.
// ===========================================================================
__device__ __forceinline__ void
gemm_core2(const __half* __restrict__ A, int lda,
           const __half* __restrict__ B, int ldb,
           void* __restrict__ Dv, int ldd, int d_half,
           const float* __restrict__ bias, const float* __restrict__ bias2,
           int bias_mode, int relu,
           int Kdim, int m0, int n0, __half* smem)
{
    const uint32_t sb32 = smem_u32(smem);
    const int tid = threadIdx.x;
    const int wid = tid >> 5, lane = tid & 31;
    const int gid = lane >> 2, tig = lane & 3;
    const int wm = (wid >> 2) << 5;
    const int wn = (wid & 3) << 5;

    const int lrow = tid >> 3;
    const int lh   = (tid & 7) << 3;
    const __half* gA = A + (size_t)(m0 + lrow) * lda + lh;
    const __half* gB = B + (size_t)(n0 + lrow) * ldb + lh;
    const uint32_t dstA = sb32 + (uint32_t)(lrow * AROW + lh) * 2u;
    const uint32_t dstB = dstA + OPER_H * 2u;

    const int lm = lane & 7, lq3 = (lane >> 3) & 1, lq4 = (lane >> 4) & 1;
    const uint32_t offA = (uint32_t)(((wm + lm + lq3 * 8) * AROW) + lq4 * 8) * 2u;
    const uint32_t offB = (uint32_t)(OPER_H + ((wn + lm + lq4 * 8) * AROW) + lq3 * 8) * 2u;

    float acc[2][4][4];
#pragma unroll
    for (int i = 0; i < 2; ++i)
#pragma unroll
        for (int j = 0; j < 4; ++j)
#pragma unroll
            for (int r = 0; r < 4; ++r) acc[i][j][r] = 0.f;

    const int nk = Kdim >> 6;

    auto load_stage = [&](int kt, int sl) {
        uint32_t soff = (uint32_t)(sl * STG_H) * 2u;
        const __half* ga = gA + kt * 64;
        const __half* gb = gB + kt * 64;
#pragma unroll
        for (int j = 0; j < 2; ++j) {
            cpa16(dstA + soff + (uint32_t)(j * 64 * AROW) * 2u, ga + (size_t)(64 * j) * lda);
            cpa16(dstB + soff + (uint32_t)(j * 64 * AROW) * 2u, gb + (size_t)(64 * j) * ldb);
        }
    };

    load_stage(0, 0); CP_COMMIT();
    if (nk > 1) { load_stage(1, 1); CP_COMMIT(); }
    if (nk > 2) { load_stage(2, 2); CP_COMMIT(); }

    uint32_t af[2][2][4], bf[2][4][2];

    for (int ks = 0; ks < nk; ++ks) {
        if (ks >= nk - 3) { CP_WAIT(0); } else { CP_WAIT(2); }
        __syncthreads();
        if (ks + 3 < nk) { load_stage(ks + 3, (ks + 3) % STAGES2); CP_COMMIT(); }

        const uint32_t St_b = sb32 + (uint32_t)((ks % STAGES2) * STG_H) * 2u;

#pragma unroll
        for (int mt = 0; mt < 2; ++mt)
            ldsm_x4(af[0][mt][0], af[0][mt][1], af[0][mt][2], af[0][mt][3],
                    St_b + offA + (uint32_t)(mt * 16 * AROW) * 2u);
#pragma unroll
        for (int np = 0; np < 2; ++np)
            ldsm_x4(bf[0][2 * np][0], bf[0][2 * np][1], bf[0][2 * np + 1][0], bf[0][2 * np + 1][1],
                    St_b + offB + (uint32_t)(np * 16 * AROW) * 2u);

#pragma unroll
        for (int kk = 0; kk < 4; ++kk) {
            const int cur = kk & 1, nxt = cur ^ 1;
            if (kk < 3) {
                const uint32_t k1b = (uint32_t)((kk + 1) * 16) * 2u;
#pragma unroll
                for (int mt = 0; mt < 2; ++mt)
                    ldsm_x4(af[nxt][mt][0], af[nxt][mt][1], af[nxt][mt][2], af[nxt][mt][3],
                            St_b + offA + (uint32_t)(mt * 16 * AROW) * 2u + k1b);
#pragma unroll
                for (int np = 0; np < 2; ++np)
                    ldsm_x4(bf[nxt][2 * np][0], bf[nxt][2 * np][1],
                            bf[nxt][2 * np + 1][0], bf[nxt][2 * np + 1][1],
                            St_b + offB + (uint32_t)(np * 16 * AROW) * 2u + k1b);
            }
#pragma unroll
            for (int mt = 0; mt < 2; ++mt)
#pragma unroll
                for (int nt = 0; nt < 4; ++nt)
                    mma_f16(acc[mt][nt], af[cur][mt], bf[cur][nt]);
        }
    }

    const bool rowb = (bias_mode == 1 || bias_mode == 3);
    const bool colb = (bias_mode == 2 || bias_mode == 3);
    const float* colv = (bias_mode == 3) ? bias2 : bias;

    float*  Df = (float*)Dv;
    __half* Dh = (__half*)Dv;
#pragma unroll
    for (int mt = 0; mt < 2; ++mt) {
        const int r0 = m0 + wm + mt * 16 + gid;
        const float bm0 = rowb ? __ldg(&bias[r0]) : 0.f;
        const float bm1 = rowb ? __ldg(&bias[r0 + 8]) : 0.f;
#pragma unroll
        for (int nt = 0; nt < 4; ++nt) {
            const int col = n0 + wn + nt * 8 + tig * 2;
            float2 cb = make_float2(0.f, 0.f);
            if (colb) cb = *(const float2*)(colv + col);
            float v0 = acc[mt][nt][0] + bm0 + cb.x;
            float v1 = acc[mt][nt][1] + bm0 + cb.y;
            float v2 = acc[mt][nt][2] + bm1 + cb.x;
            float v3 = acc[mt][nt][3] + bm1 + cb.y;
            if (relu) {
                v0 = fmaxf(v0, 0.f); v1 = fmaxf(v1, 0.f);
                v2 = fmaxf(v2, 0.f); v3 = fmaxf(v3, 0.f);
            }
            if (d_half) {
                *(__half2*)(Dh + (size_t)r0 * ldd + col) = __floats2half2_rn(v0, v1);
                *(__half2*)(Dh + (size_t)(r0 + 8) * ldd + col) = __floats2half2_rn(v2, v3);
            } else {
                *(float2*)(Df + (size_t)r0 * ldd + col) = make_float2(v0, v1);
                *(float2*)(Df + (size_t)(r0 + 8) * ldd + col) = make_float2(v2, v3);
            }
        }
    }
}

// generic batched GEMM (v2 core). sBias: per-z offset applied to bias & bias2.
__global__ void __launch_bounds__(512, 1)
gemm_v2(const __half* __restrict__ A, size_t sA, int lda,
        const __half* __restrict__ B, size_t sB, int ldb,
        void* __restrict__ Dv, size_t sD, int ldd, int d_half,
        const float* __restrict__ bias, const float* __restrict__ bias2,
        size_t sBias, int bias_mode, int relu, int Kdim)
{
    extern __shared__ __half smem[];
    void* Dp = d_half ? (void*)((__half*)Dv + (size_t)blockIdx.z * sD)
                      : (void*)((float*)Dv + (size_t)blockIdx.z * sD);
    const float* b1 = bias ? bias + (size_t)blockIdx.z * sBias : nullptr;
    const float* b2 = bias2 ? bias2 + (size_t)blockIdx.z * sBias : nullptr;
    gemm_core2(A + (size_t)blockIdx.z * sA, lda,
               B + (size_t)blockIdx.z * sB, ldb,
               Dp, ldd, d_half, b1, b2, bias_mode, relu, Kdim,
               blockIdx.y * 128, blockIdx.x * 128, smem);
}

// ===========================================================================
// elementwise
// ===========================================================================
__global__ void stats_kernel(const float* __restrict__ content,
                             const float* __restrict__ style,
                             float2* __restrict__ stats) {
    const int id = blockIdx.x;
    const float* x = (id < Bn * Cn) ? content : style;
    const size_t base = (size_t)(id & (Bn * Cn - 1)) * Nn;
    const int tid = threadIdx.x;
    float s = 0.f, s2 = 0.f;
#pragma unroll
    for (int i = 0; i < 16; ++i) {
        float t = x[base + tid + i * 256];
        s += t; s2 += t * t;
    }
#pragma unroll
    for (int o = 16; o > 0; o >>= 1) {
        s  += __shfl_xor_sync(0xffffffffu, s, o);
        s2 += __shfl_xor_sync(0xffffffffu, s2, o);
    }
    __shared__ float sh[16];
    int warp = tid >> 5, lane = tid & 31;
    if (lane == 0) { sh[warp] = s; sh[8 + warp] = s2; }
    __syncthreads();
    if (tid == 0) {
        float S = 0.f, S2 = 0.f;
        for (int w = 0; w < 8; ++w) { S += sh[w]; S2 += sh[8 + w]; }
        float mean = S * (1.f / Nn);
        float var  = S2 * (1.f / Nn) - mean * mean;
        stats[id] = make_float2(mean, rsqrtf(var + 1e-5f));
    }
}

// fused transpose: g=0: content -> NCt (normed); g=1: style -> NSt + St (one read)
__global__ void transpose_nh(const float* __restrict__ content,
                             const float* __restrict__ style,
                             const float2* __restrict__ stats,
                             __half* __restrict__ NCt, __half* __restrict__ NSt,
                             __half* __restrict__ St) {
    __shared__ float t[32][33];
    const int g = blockIdx.z >> 2;
    const int b = blockIdx.z & 3;
    const float* in = (g == 0) ? content : style;
    const float2* st = (g == 0) ? stats : stats + Bn * Cn;

    const float* ib = in + (size_t)b * Cn * Nn;
    int c0 = blockIdx.x * 32, r0 = blockIdx.y * 32;
#pragma unroll
    for (int j = 0; j < 4; ++j)
        t[threadIdx.y + 8 * j][threadIdx.x] =
            ib[(size_t)(r0 + threadIdx.y + 8 * j) * Nn + c0 + threadIdx.x];
    __syncthreads();
    const int c = r0 + threadIdx.x;
    const float2 ms = __ldg(&st[b * Cn + c]);
    if (g == 0) {
        __half* ob = NCt + (size_t)b * Cn * Nn;
#pragma unroll
        for (int j = 0; j < 4; ++j) {
            float v = t[threadIdx.x][threadIdx.y + 8 * j];
            ob[(size_t)(c0 + threadIdx.y + 8 * j) * Cn + c] =
                __float2half_rn((v - ms.x) * ms.y);
        }
    } else {
        __half* obN = NSt + (size_t)b * Cn * Nn;
        __half* obS = St + (size_t)b * Cn * Nn;
#pragma unroll
        for (int j = 0; j < 4; ++j) {
            float v = t[threadIdx.x][threadIdx.y + 8 * j];
            size_t o = (size_t)(c0 + threadIdx.y + 8 * j) * Cn + c;
            obN[o] = __float2half_rn((v - ms.x) * ms.y);
            obS[o] = __float2half_rn(v);
        }
    }
}

// prep: WV/WGB to half, bias stack
__global__ void prep_weights(const float* __restrict__ Wv, const float* __restrict__ Wg,
                             const float* __restrict__ Wb, const float* __restrict__ bg,
                             const float* __restrict__ bb,
                             __half* __restrict__ WV, __half* __restrict__ WGB,
                             float* __restrict__ bGB) {
    int i = blockIdx.x * 256 + threadIdx.x;
    if (i < WN) {
        WV[i] = __float2half_rn(Wv[i]);
        WGB[i] = __float2half_rn(Wg[i]);
        WGB[WN + i] = __float2half_rn(Wb[i]);
    }
    if (i < TWO_C) bGB[i] = (i < Cn) ? bg[i] : bb[i - Cn];
}

// weight transpose fp32[co][ci] -> half[ci][co]; z=0: Wq->WQt, z=1: Wk->WKt
__global__ void wtrans_kernel(const float* __restrict__ Wq, const float* __restrict__ Wk,
                              __half* __restrict__ WQt, __half* __restrict__ WKt) {
    __shared__ float t[32][33];
    const float* in = blockIdx.z ? Wk : Wq;
    __half* out = blockIdx.z ? WKt : WQt;
    int c0 = blockIdx.x * 32, r0 = blockIdx.y * 32;
#pragma unroll
    for (int j = 0; j < 4; ++j)
        t[threadIdx.y + 8 * j][threadIdx.x] =
            in[(size_t)(r0 + threadIdx.y + 8 * j) * Cn + c0 + threadIdx.x];
    __syncthreads();
#pragma unroll
    for (int j = 0; j < 4; ++j)
        out[(size_t)(c0 + threadIdx.y + 8 * j) * Cn + r0 + threadIdx.x] =
            __float2half_rn(t[threadIdx.x][threadIdx.y + 8 * j]);
}

// u[ci]=sum_co Wk[co,ci]*bq[co]; v[ci]=sum_co Wq[co,ci]*bk[co]; c0=bq.bk
__global__ void uvc_kernel(const float* __restrict__ Wq, const float* __restrict__ Wk,
                           const float* __restrict__ bq, const float* __restrict__ bk,
                           float* __restrict__ uvc) {
    int ci = threadIdx.x;   // 512
    float su = 0.f, sv = 0.f;
    for (int co = 0; co < Cn; ++co) {
        su += Wk[(size_t)co * Cn + ci] * bq[co];
        sv += Wq[(size_t)co * Cn + ci] * bk[co];
    }
    uvc[ci] = su;
    uvc[Cn + ci] = sv;
    if (ci == 0) {
        float s = 0.f;
        for (int co = 0; co < Cn; ++co) s += bq[co] * bk[co];
        uvc[2 * Cn] = s;
    }
}

// out[row] = dot(X[row, 0..C), v) + (c0p ? *c0p : 0); warp per row
__global__ void rowdot_kernel(const __half* __restrict__ X, const float* __restrict__ v,
                              const float* __restrict__ c0p, float* __restrict__ out) {
    const int warp = threadIdx.x >> 5, lane = threadIdx.x & 31;
    const size_t row = (size_t)blockIdx.x * 8 + warp;
    const __half* xr = X + row * Cn + lane * 16;
    const float* vr = v + lane * 16;
    float s = 0.f;
#pragma unroll
    for (int i = 0; i < 8; ++i) {
        float2 f = __half22float2(*(const __half2*)(xr + 2 * i));
        s += f.x * vr[2 * i] + f.y * vr[2 * i + 1];
    }
#pragma unroll
    for (int o = 16; o > 0; o >>= 1)
        s += __shfl_xor_sync(0xffffffffu, s, o);
    if (lane == 0) out[row] = s + (c0p ? __ldg(c0p) : 0.f);
}

// softmax over 4096 fp32 scores -> half probs in place (paired indexing)
__global__ void softmax_kernel(float* __restrict__ S) {
    const int tid = threadIdx.x;
    float* rowf = S + (size_t)blockIdx.x * Nn;
    __half* rowh = (__half*)rowf;
    float2 v[8];
    float mx = -INFINITY;
#pragma unroll
    for (int i = 0; i < 8; ++i) {
        v[i] = *(const float2*)(rowf + tid * 2 + i * 512);
        mx = fmaxf(mx, fmaxf(v[i].x, v[i].y));
    }
#pragma unroll
    for (int o = 16; o > 0; o >>= 1)
        mx = fmaxf(mx, __shfl_xor_sync(0xffffffffu, mx, o));
    __shared__ float sh[16];
    int warp = tid >> 5, lane = tid & 31;
    if (lane == 0) sh[warp] = mx;
    __syncthreads();
    if (tid == 0) {
        float m = sh[0];
        for (int w = 1; w < 8; ++w) m = fmaxf(m, sh[w]);
        sh[0] = m;
    }
    __syncthreads();
    mx = sh[0];
    float s = 0.f;
#pragma unroll
    for (int i = 0; i < 8; ++i) {
        v[i].x = __expf(v[i].x - mx);
        v[i].y = __expf(v[i].y - mx);
        s += v[i].x + v[i].y;
    }
#pragma unroll
    for (int o = 16; o > 0; o >>= 1)
        s += __shfl_xor_sync(0xffffffffu, s, o);
    if (lane == 0) sh[8 + warp] = s;
    __syncthreads();
    if (tid == 0) {
        float t = 0.f;
        for (int w = 0; w < 8; ++w) t += sh[8 + w];
        sh[8] = t;
    }
    __syncthreads();
    float inv = 1.f / sh[8];
#pragma unroll
    for (int i = 0; i < 8; ++i)
        *(__half2*)(rowh + tid * 2 + i * 512) =
            __floats2half2_rn(v[i].x * inv, v[i].y * inv);
}

// combine (half gamma/beta)
__global__ void combine_kernel(const float* __restrict__ content,
                               const float2* __restrict__ stats,
                               const __half* __restrict__ GBh,
                               const float* __restrict__ sw, const float* __restrict__ sb,
                               float* __restrict__ out) {
    size_t i4 = (size_t)blockIdx.x * blockDim.x + threadIdx.x;
    size_t idx = i4 * 4;
    if (idx >= SZ_BCN) return;
    size_t n = idx & (Nn - 1);
    size_t bc = idx >> 12;
    int c = (int)(bc & (Cn - 1));
    int b = (int)(bc >> 9);
    float2 ms = __ldg(&stats[b * Cn + c]);
    float w = sw[c] * ms.y;
    float base = sb[c] - ms.x * ms.y * sw[c];
    size_t gidx = (((size_t)b * TWO_C + c) * Nn) + n;
    float4 x = *(const float4*)(content + idx);
    __half2 g01 = *(const __half2*)(GBh + gidx);
    __half2 g23 = *(const __half2*)(GBh + gidx + 2);
    __half2 b01 = *(const __half2*)(GBh + gidx + (size_t)Cn * Nn);
    __half2 b23 = *(const __half2*)(GBh + gidx + (size_t)Cn * Nn + 2);
    float2 gf01 = __half22float2(g01), gf23 = __half22float2(g23);
    float2 bf01 = __half22float2(b01), bf23 = __half22float2(b23);
    float4 r;
    r.x = (x.x * w + base) * gf01.x + bf01.x;
    r.y = (x.y * w + base) * gf01.y + bf01.y;
    r.z = (x.z * w + base) * gf23.x + bf23.x;
    r.w = (x.w * w + base) * gf23.y + bf23.y;
    *(float4*)(out + idx) = r;
}

// ===========================================================================
// launch
// ===========================================================================
extern "C" void kernel_launch(void* const* d_in, const int* in_sizes, int n_in,
                              void* d_out, int out_size) {
    const float* content = (const float*)d_in[0];
    const float* style   = (const float*)d_in[1];
    const float* Wq = (const float*)d_in[2];  const float* bq = (const float*)d_in[3];
    const float* Wk = (const float*)d_in[4];  const float* bk = (const float*)d_in[5];
    const float* Wv = (const float*)d_in[6];  const float* bv = (const float*)d_in[7];
    const float* Wg = (const float*)d_in[8];  const float* bg = (const float*)d_in[9];
    const float* Wb = (const float*)d_in[10]; const float* bb = (const float*)d_in[11];
    const float* sw = (const float*)d_in[12]; const float* sb = (const float*)d_in[13];
    float* out = (float*)d_out;

    float *S, *bGB, *uvc, *rq, *cs;
    float2* stats;
    __half *NCt, *NSt, *St, *Th, *V, *STYt, *GBh, *WQt, *WKt, *Mh, *WV, *WGB;
    cudaGetSymbolAddress((void**)&NCt, g_NCt);
    cudaGetSymbolAddress((void**)&NSt, g_NSt);
    cudaGetSymbolAddress((void**)&St, g_St);
    cudaGetSymbolAddress((void**)&Th, g_Th);
    cudaGetSymbolAddress((void**)&V, g_V);
    cudaGetSymbolAddress((void**)&STYt, g_STYt);
    cudaGetSymbolAddress((void**)&GBh, g_GBh);
    cudaGetSymbolAddress((void**)&S, g_S);
    cudaGetSymbolAddress((void**)&WQt, g_WQt);
    cudaGetSymbolAddress((void**)&WKt, g_WKt);
    cudaGetSymbolAddress((void**)&Mh, g_Mh);
    cudaGetSymbolAddress((void**)&WV, g_WV);
    cudaGetSymbolAddress((void**)&WGB, g_WGB);
    cudaGetSymbolAddress((void**)&bGB, g_bGB);
    cudaGetSymbolAddress((void**)&uvc, g_uvc);
    cudaGetSymbolAddress((void**)&rq, g_rq);
    cudaGetSymbolAddress((void**)&cs, g_cs);
    cudaGetSymbolAddress((void**)&stats, g_stats);

    static bool attr_set = false;
    if (!attr_set) {
        cudaFuncSetAttribute(gemm_v2, cudaFuncAttributeMaxDynamicSharedMemorySize, DYN_SMEM2);
        attr_set = true;
    }

    const size_t strBCN = (size_t)Cn * Nn;
    const size_t strS   = (size_t)Nn * Nn;
    const size_t strGB  = (size_t)TWO_C * Nn;

    // 0. weight prep
    prep_weights<<<(WN + 255) / 256, 256>>>(Wv, Wg, Wb, bg, bb, WV, WGB, bGB);
    wtrans_kernel<<<dim3(16, 16, 2), dim3(32, 8)>>>(Wq, Wk, WQt, WKt);
    uvc_kernel<<<1, Cn>>>(Wq, Wk, bq, bk, uvc);

    // 1. per-channel stats
    stats_kernel<<<2 * Bn * Cn, 256>>>(content, style, stats);

    // 2. fused norm+transpose
    dim3 tb(32, 8);
    dim3 tg(Nn / 32, Cn / 32, 2 * Bn);
    transpose_nh<<<tg, tb>>>(content, style, stats, NCt, NSt, St);

    // 3. M'[cj,ci] = sum_co Wk[co,cj] Wq[co,ci]  (tiny GEMM, half out)
    gemm_v2<<<dim3(4, 4, 1), 512, DYN_SMEM2>>>(WKt, 0, Cn, WQt, 0, Cn,
                                               Mh, 0, Cn, 1, nullptr, nullptr, 0, 0, 0, Cn);

    // 4. V conv: V[co,s] = WV[co,c] . St[s,c]^T (+bv rows), half out
    gemm_v2<<<dim3(32, 4, Bn), 512, DYN_SMEM2>>>(WV, 0, Cn, St, strBCN, Cn,
                                                 V, strBCN, Nn, 1, bv, nullptr, 0, 1, 0, Cn);

    // 5. T = NCt . M'^T : Th[q,cj], half out
    gemm_v2<<<dim3(4, 32, Bn), 512, DYN_SMEM2>>>(NCt, strBCN, Cn, Mh, 0, Cn,
                                                 Th, strBCN, Cn, 1, nullptr, nullptr, 0, 0, 0, Cn);

    // 6. rq = NCt . v ; cs = NSt . u + c0
    rowdot_kernel<<<Bn * Nn / 8, 256>>>(NCt, uvc + Cn, nullptr, rq);
    rowdot_kernel<<<Bn * Nn / 8, 256>>>(NSt, uvc, uvc + 2 * Cn, cs);

    // 7. scores: S[q,s] = Th[q,cj] . NSt[s,cj]^T + rq[q] + cs[s], fp32 out
    gemm_v2<<<dim3(32, 32, Bn), 512, DYN_SMEM2>>>(Th, strBCN, Cn, NSt, strBCN, Cn,
                                                  S, strS, Nn, 0, rq, cs, Nn, 3, 0, Cn);

    // 8. softmax -> half probs in place
    softmax_kernel<<<Bn * Nn, 256>>>(S);

    // 9. PV: STYt[q,c] = P[q,s] . V[c,s]^T, half out
    gemm_v2<<<dim3(4, 32, Bn), 512, DYN_SMEM2>>>((const __half*)S, 2 * strS, 2 * Nn,
                                                 V, strBCN, Nn,
                                                 STYt, strBCN, Cn, 1, nullptr, nullptr, 0, 0, 0, Nn);

    // 10. gamma/beta conv: +bGB rows, relu, half out
    gemm_v2<<<dim3(32, 8, Bn), 512, DYN_SMEM2>>>(WGB, 0, Cn, STYt, strBCN, Cn,
                                                 GBh, strGB, Nn, 1, bGB, nullptr, 0, 1, 1, Cn);

    // 11. combine
    combine_kernel<<<(unsigned)((SZ_BCN / 4 + 255) / 256), 256>>>(
        content, stats, GBh, sw, sb, out);
}

// round 17
// speedup vs baseline: 1.1599x; 1.1599x over previous
#include <cuda_runtime.h>
#include <cuda_fp16.h>
#include <math.h>
#include <stdint.h>

#define Bn 4
#define Cn 512
#define Nn 4096
#define TWO_C 1024
#define WN (Cn * Cn)

constexpr size_t SZ_BCN = (size_t)Bn * Cn * Nn;
constexpr size_t SZ_GB  = (size_t)Bn * TWO_C * Nn;
constexpr size_t SZ_S   = (size_t)Bn * Nn * Nn;

// ---- scratch ----
__device__ __half g_NCt[SZ_BCN];
__device__ __half g_NSt[SZ_BCN];
__device__ __half g_St[SZ_BCN];
__device__ __half g_Qt[SZ_BCN];
__device__ __half g_Kt[SZ_BCN];
__device__ __half g_V[SZ_BCN];
__device__ __half g_STYt[SZ_BCN];
__device__ __half g_GBh[SZ_GB];      // gamma/beta, half
__device__ float  g_S[SZ_S];
__device__ __half g_WQ[WN];
__device__ __half g_WK[WN];
__device__ __half g_WV[WN];
__device__ __half g_WGB[TWO_C * Cn];
__device__ float  g_bGB[TWO_C];
__device__ float2 g_stats[2 * Bn * Cn];

// ===========================================================================
// helpers
// ===========================================================================
__device__ __forceinline__ uint32_t smem_u32(const void* p) {
    uint32_t a;
    asm("{ .reg .u64 t; cvta.to.shared.u64 t, %1; cvt.u32.u64 %0, t; }" : "=r"(a) : "l"(p));
    return a;
}
__device__ __forceinline__ void cpa16(uint32_t d, const void* s) {
    asm volatile("cp.async.cg.shared.global [%0], [%1], 16;\n" :: "r"(d), "l"(s));
}
#define CP_COMMIT() asm volatile("cp.async.commit_group;\n" ::: "memory")
#define CP_WAIT(n)  asm volatile("cp.async.wait_group %0;\n" :: "n"(n) : "memory")

__device__ __forceinline__ void mma_f16(float* c, const uint32_t* a, const uint32_t* b) {
    asm volatile(
        "mma.sync.aligned.m16n8k16.row.col.f32.f16.f16.f32 "
        "{%0,%1,%2,%3}, {%4,%5,%6,%7}, {%8,%9}, {%0,%1,%2,%3};"
        : "+f"(c[0]), "+f"(c[1]), "+f"(c[2]), "+f"(c[3])
        : "r"(a[0]), "r"(a[1]), "r"(a[2]), "r"(a[3]), "r"(b[0]), "r"(b[1]));
}
__device__ __forceinline__ void ldsm_x4(uint32_t& r0, uint32_t& r1, uint32_t& r2, uint32_t& r3,
                                        uint32_t addr) {
    asm volatile("ldmatrix.sync.aligned.m8n8.x4.shared.b16 {%0,%1,%2,%3}, [%4];"
                 : "=r"(r0), "=r"(r1), "=r"(r2), "=r"(r3) : "r"(addr));
}

#define STAGES2 4
#define AROW 72
#define OPER_H (128 * AROW)
#define STG_H  (2 * OPER_H)
#define DYN_SMEM2 (STAGES2 * STG_H * 2)   // 147456 B

// ===========================================================================
// v2 core (device): 512 threads, 1 CTA/SM, warp grid 4x4, warp 32x32, BK=64,
// 4-stage cp.async, double-buffered ldmatrix fragments.
// D[M,N] = A[M,K] * B[N,K]^T. bias_mode 0/1(row)/2(col); relu; d_half.
// ===========================================================================
__device__ __forceinline__ void
gemm_core2(const __half* __restrict__ A, int lda,
           const __half* __restrict__ B, int ldb,
           void* __restrict__ Dv, int ldd, int d_half,
           const float* __restrict__ bias, int bias_mode, int relu,
           int Kdim, int m0, int n0, __half* smem)
{
    const uint32_t sb32 = smem_u32(smem);
    const int tid = threadIdx.x;
    const int wid = tid >> 5, lane = tid & 31;
    const int gid = lane >> 2, tig = lane & 3;
    const int wm = (wid >> 2) << 5;
    const int wn = (wid & 3) << 5;

    const int lrow = tid >> 3;
    const int lh   = (tid & 7) << 3;
    const __half* gA = A + (size_t)(m0 + lrow) * lda + lh;
    const __half* gB = B + (size_t)(n0 + lrow) * ldb + lh;
    const uint32_t dstA = sb32 + (uint32_t)(lrow * AROW + lh) * 2u;
    const uint32_t dstB = dstA + OPER_H * 2u;

    const int lm = lane & 7, lq3 = (lane >> 3) & 1, lq4 = (lane >> 4) & 1;
    const uint32_t offA = (uint32_t)(((wm + lm + lq3 * 8) * AROW) + lq4 * 8) * 2u;
    const uint32_t offB = (uint32_t)(OPER_H + ((wn + lm + lq4 * 8) * AROW) + lq3 * 8) * 2u;

    float acc[2][4][4];
#pragma unroll
    for (int i = 0; i < 2; ++i)
#pragma unroll
        for (int j = 0; j < 4; ++j)
#pragma unroll
            for (int r = 0; r < 4; ++r) acc[i][j][r] = 0.f;

    const int nk = Kdim >> 6;

    auto load_stage = [&](int kt, int sl) {
        uint32_t soff = (uint32_t)(sl * STG_H) * 2u;
        const __half* ga = gA + kt * 64;
        const __half* gb = gB + kt * 64;
#pragma unroll
        for (int j = 0; j < 2; ++j) {
            cpa16(dstA + soff + (uint32_t)(j * 64 * AROW) * 2u, ga + (size_t)(64 * j) * lda);
            cpa16(dstB + soff + (uint32_t)(j * 64 * AROW) * 2u, gb + (size_t)(64 * j) * ldb);
        }
    };

    load_stage(0, 0); CP_COMMIT();
    if (nk > 1) { load_stage(1, 1); CP_COMMIT(); }
    if (nk > 2) { load_stage(2, 2); CP_COMMIT(); }

    uint32_t af[2][2][4], bf[2][4][2];

    for (int ks = 0; ks < nk; ++ks) {
        if (ks >= nk - 3) { CP_WAIT(0); } else { CP_WAIT(2); }
        __syncthreads();
        if (ks + 3 < nk) { load_stage(ks + 3, (ks + 3) % STAGES2); CP_COMMIT(); }

        const uint32_t St_b = sb32 + (uint32_t)((ks % STAGES2) * STG_H) * 2u;

#pragma unroll
        for (int mt = 0; mt < 2; ++mt)
            ldsm_x4(af[0][mt][0], af[0][mt][1], af[0][mt][2], af[0][mt][3],
                    St_b + offA + (uint32_t)(mt * 16 * AROW) * 2u);
#pragma unroll
        for (int np = 0; np < 2; ++np)
            ldsm_x4(bf[0][2 * np][0], bf[0][2 * np][1], bf[0][2 * np + 1][0], bf[0][2 * np + 1][1],
                    St_b + offB + (uint32_t)(np * 16 * AROW) * 2u);

#pragma unroll
        for (int kk = 0; kk < 4; ++kk) {
            const int cur = kk & 1, nxt = cur ^ 1;
            if (kk < 3) {
                const uint32_t k1b = (uint32_t)((kk + 1) * 16) * 2u;
#pragma unroll
                for (int mt = 0; mt < 2; ++mt)
                    ldsm_x4(af[nxt][mt][0], af[nxt][mt][1], af[nxt][mt][2], af[nxt][mt][3],
                            St_b + offA + (uint32_t)(mt * 16 * AROW) * 2u + k1b);
#pragma unroll
                for (int np = 0; np < 2; ++np)
                    ldsm_x4(bf[nxt][2 * np][0], bf[nxt][2 * np][1],
                            bf[nxt][2 * np + 1][0], bf[nxt][2 * np + 1][1],
                            St_b + offB + (uint32_t)(np * 16 * AROW) * 2u + k1b);
            }
#pragma unroll
            for (int mt = 0; mt < 2; ++mt)
#pragma unroll
                for (int nt = 0; nt < 4; ++nt)
                    mma_f16(acc[mt][nt], af[cur][mt], bf[cur][nt]);
        }
    }

    float*  Df = (float*)Dv;
    __half* Dh = (__half*)Dv;
#pragma unroll
    for (int mt = 0; mt < 2; ++mt) {
        const int r0 = m0 + wm + mt * 16 + gid;
        const float bm0 = (bias_mode == 1) ? __ldg(&bias[r0]) : 0.f;
        const float bm1 = (bias_mode == 1) ? __ldg(&bias[r0 + 8]) : 0.f;
#pragma unroll
        for (int nt = 0; nt < 4; ++nt) {
            const int col = n0 + wn + nt * 8 + tig * 2;
            float2 bn2 = make_float2(bm0, bm0);
            float2 bn3 = make_float2(bm1, bm1);
            if (bias_mode == 2) {
                bn2 = *(const float2*)(bias + col);
                bn3 = bn2;
            }
            float v0 = acc[mt][nt][0] + bn2.x;
            float v1 = acc[mt][nt][1] + bn2.y;
            float v2 = acc[mt][nt][2] + bn3.x;
            float v3 = acc[mt][nt][3] + bn3.y;
            if (relu) {
                v0 = fmaxf(v0, 0.f); v1 = fmaxf(v1, 0.f);
                v2 = fmaxf(v2, 0.f); v3 = fmaxf(v3, 0.f);
            }
            if (d_half) {
                *(__half2*)(Dh + (size_t)r0 * ldd + col) = __floats2half2_rn(v0, v1);
                *(__half2*)(Dh + (size_t)(r0 + 8) * ldd + col) = __floats2half2_rn(v2, v3);
            } else {
                *(float2*)(Df + (size_t)r0 * ldd + col) = make_float2(v0, v1);
                *(float2*)(Df + (size_t)(r0 + 8) * ldd + col) = make_float2(v2, v3);
            }
        }
    }
}

// generic batched GEMM (v2 core)
__global__ void __launch_bounds__(512, 1)
gemm_v2(const __half* __restrict__ A, size_t sA, int lda,
        const __half* __restrict__ B, size_t sB, int ldb,
        void* __restrict__ Dv, size_t sD, int ldd, int d_half,
        const float* __restrict__ bias, int bias_mode, int relu, int Kdim)
{
    extern __shared__ __half smem[];
    void* Dp = d_half ? (void*)((__half*)Dv + (size_t)blockIdx.z * sD)
                      : (void*)((float*)Dv + (size_t)blockIdx.z * sD);
    gemm_core2(A + (size_t)blockIdx.z * sA, lda,
               B + (size_t)blockIdx.z * sB, ldb,
               Dp, ldd, d_half, bias, bias_mode, relu, Kdim,
               blockIdx.y * 128, blockIdx.x * 128, smem);
}

// fused Q/K/V convs (v2 core): grid (32, 4, 12). z>>2: 0=Q 1=K 2=V; z&3 = batch
__global__ void __launch_bounds__(512, 1)
qkv_gemm2(const __half* __restrict__ NCt, const __half* __restrict__ NSt,
          const __half* __restrict__ St,
          const __half* __restrict__ WQ, const __half* __restrict__ WK,
          const __half* __restrict__ WV,
          __half* __restrict__ Qt, __half* __restrict__ Kt, __half* __restrict__ V,
          const float* __restrict__ bq, const float* __restrict__ bk,
          const float* __restrict__ bv)
{
    extern __shared__ __half smem[];
    const int g = blockIdx.z >> 2;
    const size_t boff = (size_t)(blockIdx.z & 3) * ((size_t)Cn * Nn);

    if (g < 2) {
        const __half* Aop = (g == 0 ? NCt : NSt) + boff;
        const __half* Bop = (g == 0 ? WQ : WK);
        __half* D = (g == 0 ? Qt : Kt) + boff;
        const float* bias = (g == 0 ? bq : bk);
        gemm_core2(Aop, Cn, Bop, Cn, D, Cn, 1, bias, 2, 0, Cn,
                   blockIdx.x * 128, blockIdx.y * 128, smem);
    } else {
        gemm_core2(WV, Cn, St + boff, Cn, V + boff, Nn, 1, bv, 1, 0, Cn,
                   blockIdx.y * 128, blockIdx.x * 128, smem);
    }
}

// ===========================================================================
// elementwise
// ===========================================================================
// stats with float4 loads: each thread covers 16 elements as 4x float4
__global__ void stats_kernel(const float* __restrict__ content,
                             const float* __restrict__ style,
                             float2* __restrict__ stats) {
    const int id = blockIdx.x;
    const float* x = (id < Bn * Cn) ? content : style;
    const size_t base = (size_t)(id & (Bn * Cn - 1)) * Nn;
    const int tid = threadIdx.x;
    float s = 0.f, s2 = 0.f;
#pragma unroll
    for (int i = 0; i < 4; ++i) {
        float4 v = *(const float4*)(x + base + tid * 4 + i * 1024);
        s += v.x + v.y + v.z + v.w;
        s2 += v.x * v.x + v.y * v.y + v.z * v.z + v.w * v.w;
    }
#pragma unroll
    for (int o = 16; o > 0; o >>= 1) {
        s  += __shfl_xor_sync(0xffffffffu, s, o);
        s2 += __shfl_xor_sync(0xffffffffu, s2, o);
    }
    __shared__ float sh[16];
    int warp = tid >> 5, lane = tid & 31;
    if (lane == 0) { sh[warp] = s; sh[8 + warp] = s2; }
    __syncthreads();
    if (tid == 0) {
        float S = 0.f, S2 = 0.f;
        for (int w = 0; w < 8; ++w) { S += sh[w]; S2 += sh[8 + w]; }
        float mean = S * (1.f / Nn);
        float var  = S2 * (1.f / Nn) - mean * mean;
        stats[id] = make_float2(mean, rsqrtf(var + 1e-5f));
    }
}

// fused transpose: g=0: content -> NCt (normed); g=1: style -> NSt + St (one read)
__global__ void transpose_nh(const float* __restrict__ content,
                             const float* __restrict__ style,
                             const float2* __restrict__ stats,
                             __half* __restrict__ NCt, __half* __restrict__ NSt,
                             __half* __restrict__ St) {
    __shared__ float t[32][33];
    const int g = blockIdx.z >> 2;
    const int b = blockIdx.z & 3;
    const float* in = (g == 0) ? content : style;
    const float2* st = (g == 0) ? stats : stats + Bn * Cn;

    const float* ib = in + (size_t)b * Cn * Nn;
    int c0 = blockIdx.x * 32, r0 = blockIdx.y * 32;
#pragma unroll
    for (int j = 0; j < 4; ++j)
        t[threadIdx.y + 8 * j][threadIdx.x] =
            ib[(size_t)(r0 + threadIdx.y + 8 * j) * Nn + c0 + threadIdx.x];
    __syncthreads();
    const int c = r0 + threadIdx.x;
    const float2 ms = __ldg(&st[b * Cn + c]);
    if (g == 0) {
        __half* ob = NCt + (size_t)b * Cn * Nn;
#pragma unroll
        for (int j = 0; j < 4; ++j) {
            float v = t[threadIdx.x][threadIdx.y + 8 * j];
            ob[(size_t)(c0 + threadIdx.y + 8 * j) * Cn + c] =
                __float2half_rn((v - ms.x) * ms.y);
        }
    } else {
        __half* obN = NSt + (size_t)b * Cn * Nn;
        __half* obS = St + (size_t)b * Cn * Nn;
#pragma unroll
        for (int j = 0; j < 4; ++j) {
            float v = t[threadIdx.x][threadIdx.y + 8 * j];
            size_t o = (size_t)(c0 + threadIdx.y + 8 * j) * Cn + c;
            obN[o] = __float2half_rn((v - ms.x) * ms.y);
            obS[o] = __float2half_rn(v);
        }
    }
}

__global__ void prep_weights(const float* __restrict__ Wq, const float* __restrict__ Wk,
                             const float* __restrict__ Wv, const float* __restrict__ Wg,
                             const float* __restrict__ Wb, const float* __restrict__ bg,
                             const float* __restrict__ bb,
                             __half* __restrict__ WQ, __half* __restrict__ WK,
                             __half* __restrict__ WV, __half* __restrict__ WGB,
                             float* __restrict__ bGB) {
    int i = blockIdx.x * 256 + threadIdx.x;
    if (i < WN) {
        WQ[i] = __float2half_rn(Wq[i]);
        WK[i] = __float2half_rn(Wk[i]);
        WV[i] = __float2half_rn(Wv[i]);
        WGB[i] = __float2half_rn(Wg[i]);
        WGB[WN + i] = __float2half_rn(Wb[i]);
    }
    if (i < TWO_C) bGB[i] = (i < Cn) ? bg[i] : bb[i - Cn];
}

// softmax over 4096 fp32 scores -> half probs in place (paired indexing)
__global__ void softmax_kernel(float* __restrict__ S) {
    const int tid = threadIdx.x;
    float* rowf = S + (size_t)blockIdx.x * Nn;
    __half* rowh = (__half*)rowf;
    float2 v[8];
    float mx = -INFINITY;
#pragma unroll
    for (int i = 0; i < 8; ++i) {
        v[i] = *(const float2*)(rowf + tid * 2 + i * 512);
        mx = fmaxf(mx, fmaxf(v[i].x, v[i].y));
    }
#pragma unroll
    for (int o = 16; o > 0; o >>= 1)
        mx = fmaxf(mx, __shfl_xor_sync(0xffffffffu, mx, o));
    __shared__ float sh[16];
    int warp = tid >> 5, lane = tid & 31;
    if (lane == 0) sh[warp] = mx;
    __syncthreads();
    if (tid == 0) {
        float m = sh[0];
        for (int w = 1; w < 8; ++w) m = fmaxf(m, sh[w]);
        sh[0] = m;
    }
    __syncthreads();
    mx = sh[0];
    float s = 0.f;
#pragma unroll
    for (int i = 0; i < 8; ++i) {
        v[i].x = __expf(v[i].x - mx);
        v[i].y = __expf(v[i].y - mx);
        s += v[i].x + v[i].y;
    }
#pragma unroll
    for (int o = 16; o > 0; o >>= 1)
        s += __shfl_xor_sync(0xffffffffu, s, o);
    if (lane == 0) sh[8 + warp] = s;
    __syncthreads();
    if (tid == 0) {
        float t = 0.f;
        for (int w = 0; w < 8; ++w) t += sh[8 + w];
        sh[8] = t;
    }
    __syncthreads();
    float inv = 1.f / sh[8];
#pragma unroll
    for (int i = 0; i < 8; ++i)
        *(__half2*)(rowh + tid * 2 + i * 512) =
            __floats2half2_rn(v[i].x * inv, v[i].y * inv);
}

// combine: gamma/beta half
__global__ void combine_kernel(const float* __restrict__ content,
                               const float2* __restrict__ stats,
                               const __half* __restrict__ GBh,
                               const float* __restrict__ sw, const float* __restrict__ sb,
                               float* __restrict__ out) {
    size_t i4 = (size_t)blockIdx.x * blockDim.x + threadIdx.x;
    size_t idx = i4 * 4;
    if (idx >= SZ_BCN) return;
    size_t n = idx & (Nn - 1);
    size_t bc = idx >> 12;
    int c = (int)(bc & (Cn - 1));
    int b = (int)(bc >> 9);
    float2 ms = __ldg(&stats[b * Cn + c]);
    float w = sw[c] * ms.y;
    float base = sb[c] - ms.x * ms.y * sw[c];
    size_t gidx = (((size_t)b * TWO_C + c) * Nn) + n;
    float4 x = *(const float4*)(content + idx);
    __half2 g01 = *(const __half2*)(GBh + gidx);
    __half2 g23 = *(const __half2*)(GBh + gidx + 2);
    __half2 b01 = *(const __half2*)(GBh + gidx + (size_t)Cn * Nn);
    __half2 b23 = *(const __half2*)(GBh + gidx + (size_t)Cn * Nn + 2);
    float2 gf01 = __half22float2(g01), gf23 = __half22float2(g23);
    float2 bf01 = __half22float2(b01), bf23 = __half22float2(b23);
    float4 r;
    r.x = (x.x * w + base) * gf01.x + bf01.x;
    r.y = (x.y * w + base) * gf01.y + bf01.y;
    r.z = (x.z * w + base) * gf23.x + bf23.x;
    r.w = (x.w * w + base) * gf23.y + bf23.y;
    *(float4*)(out + idx) = r;
}

// ===========================================================================
// launch
// ===========================================================================
extern "C" void kernel_launch(void* const* d_in, const int* in_sizes, int n_in,
                              void* d_out, int out_size) {
    const float* content = (const float*)d_in[0];
    const float* style   = (const float*)d_in[1];
    const float* Wq = (const float*)d_in[2];  const float* bq = (const float*)d_in[3];
    const float* Wk = (const float*)d_in[4];  const float* bk = (const float*)d_in[5];
    const float* Wv = (const float*)d_in[6];  const float* bv = (const float*)d_in[7];
    const float* Wg = (const float*)d_in[8];  const float* bg = (const float*)d_in[9];
    const float* Wb = (const float*)d_in[10]; const float* bb = (const float*)d_in[11];
    const float* sw = (const float*)d_in[12]; const float* sb = (const float*)d_in[13];
    float* out = (float*)d_out;

    float *S, *bGB;
    float2* stats;
    __half *NCt, *NSt, *St, *Qt, *Kt, *V, *STYt, *GBh, *WQ, *WK, *WV, *WGB;
    cudaGetSymbolAddress((void**)&NCt, g_NCt);
    cudaGetSymbolAddress((void**)&NSt, g_NSt);
    cudaGetSymbolAddress((void**)&St, g_St);
    cudaGetSymbolAddress((void**)&Qt, g_Qt);
    cudaGetSymbolAddress((void**)&Kt, g_Kt);
    cudaGetSymbolAddress((void**)&V, g_V);
    cudaGetSymbolAddress((void**)&STYt, g_STYt);
    cudaGetSymbolAddress((void**)&GBh, g_GBh);
    cudaGetSymbolAddress((void**)&S, g_S);
    cudaGetSymbolAddress((void**)&WQ, g_WQ);
    cudaGetSymbolAddress((void**)&WK, g_WK);
    cudaGetSymbolAddress((void**)&WV, g_WV);
    cudaGetSymbolAddress((void**)&WGB, g_WGB);
    cudaGetSymbolAddress((void**)&bGB, g_bGB);
    cudaGetSymbolAddress((void**)&stats, g_stats);

    static bool attr_set = false;
    if (!attr_set) {
        cudaFuncSetAttribute(qkv_gemm2, cudaFuncAttributeMaxDynamicSharedMemorySize, DYN_SMEM2);
        cudaFuncSetAttribute(gemm_v2, cudaFuncAttributeMaxDynamicSharedMemorySize, DYN_SMEM2);
        attr_set = true;
    }

    const size_t strBCN = (size_t)Cn * Nn;
    const size_t strS   = (size_t)Nn * Nn;
    const size_t strGB  = (size_t)TWO_C * Nn;

    // 0. weights -> half, stacked bias
    prep_weights<<<(WN + 255) / 256, 256>>>(Wq, Wk, Wv, Wg, Wb, bg, bb,
                                            WQ, WK, WV, WGB, bGB);

    // 1. per-channel stats (float4 loads)
    stats_kernel<<<2 * Bn * Cn, 256>>>(content, style, stats);

    // 2. fused norm+transpose (style read once -> NSt + St)
    dim3 tb(32, 8);
    dim3 tg(Nn / 32, Cn / 32, 2 * Bn);
    transpose_nh<<<tg, tb>>>(content, style, stats, NCt, NSt, St);

    // 3. fused Q/K/V convs (v2 core)
    qkv_gemm2<<<dim3(32, 4, 12), 512, DYN_SMEM2>>>(NCt, NSt, St, WQ, WK, WV,
                                                   Qt, Kt, V, bq, bk, bv);

    // 4. scores (v2): S[q,s] = Qt[q,c] . Kt[s,c]^T, fp32 out
    gemm_v2<<<dim3(32, 32, Bn), 512, DYN_SMEM2>>>(Qt, strBCN, Cn, Kt, strBCN, Cn,
                                                  S, strS, Nn, 0, nullptr, 0, 0, Cn);

    // 5. softmax -> half probs in place
    softmax_kernel<<<Bn * Nn, 256>>>(S);

    // 6. PV (v2): STYt[q,c] = P[q,s] . V[c,s]^T, half out
    gemm_v2<<<dim3(4, 32, Bn), 512, DYN_SMEM2>>>((const __half*)S, 2 * strS, 2 * Nn,
                                                 V, strBCN, Nn,
                                                 STYt, strBCN, Cn, 1, nullptr, 0, 0, Nn);

    // 7. gamma/beta conv (v2): +bGB rows, relu, HALF out
    gemm_v2<<<dim3(32, 8, Bn), 512, DYN_SMEM2>>>(WGB, 0, Cn, STYt, strBCN, Cn,
                                                 GBh, strGB, Nn, 1, bGB, 1, 1, Cn);

    // 8. combine (half gamma/beta)
    combine_kernel<<<(unsigned)((SZ_BCN / 4 + 255) / 256), 256>>>(
        content, stats, GBh, sw, sb, out);
}